// round 4
// baseline (speedup 1.0000x reference)
#include <cuda_runtime.h>
#include <cstdint>

// Problem constants
#define NB   8192
#define ND   1024
#define NR   64
#define NRR  4096

// GEMM tiling
#define BM 128
#define BN 128
#define BK 32
#define SKEW 4
#define LDS_W (BK + SKEW)   // 36

// ---------------- static device scratch (no allocations allowed) ------------
__device__ float g_W[(size_t)NB * NRR];      // 128 MiB: per-sample generated weights
__device__ float g_u[(size_t)NB * NR];
__device__ float g_h[(size_t)NB * NR];
__device__ float g_act0[(size_t)NB * ND];
__device__ float g_act1[(size_t)NB * ND];

__device__ __forceinline__ uint32_t f2tf(float f) {
    uint32_t r;
    asm("cvt.rna.tf32.f32 %0, %1;" : "=r"(r) : "f"(f));
    return r;
}

// split f into hi (tf32) + lo (tf32 of residual); hi+lo ~ f to ~2^-22
__device__ __forceinline__ void split_tf32(float f, uint32_t& hi, uint32_t& lo) {
    hi = f2tf(f);
    lo = f2tf(f - __uint_as_float(hi));
}

#define MMA_TF32(acc, a0, a1, a2, a3, b0, b1)                                 \
    asm("mma.sync.aligned.m16n8k8.row.col.f32.tf32.tf32.f32 "                 \
        "{%0,%1,%2,%3}, {%4,%5,%6,%7}, {%8,%9}, {%0,%1,%2,%3};\n"             \
        : "+f"(acc[0]), "+f"(acc[1]), "+f"(acc[2]), "+f"(acc[3])              \
        : "r"(a0), "r"(a1), "r"(a2), "r"(a3), "r"(b0), "r"(b1))

// ---------------------------------------------------------------------------
// C[M,N] = A[M,K] @ Bm[N,K]^T   (row-major, K contiguous: "NT" GEMM)
// 3xTF32 error-compensated mma.sync: per k-slice computes
//   ahi*bhi + ahi*blo + alo*bhi  (fp32-accurate)
// CTA tile 128x128x32, 8 warps (4x2), warp tile 32x64, double-buffered smem.
// NGUARD: guard N dimension (for the U gemm where N=64 < BN).
// ---------------------------------------------------------------------------
template<bool NGUARD>
__global__ __launch_bounds__(256)
void gemm_tn_3xtf32(const float* __restrict__ A, const float* __restrict__ Bm,
                    float* __restrict__ C, int M, int N, int K)
{
    extern __shared__ uint32_t smem_[];
    uint32_t* AH = smem_;                       // 2 * BM * LDS_W
    uint32_t* AL = AH + 2 * BM * LDS_W;
    uint32_t* BH = AL + 2 * BM * LDS_W;
    uint32_t* BL = BH + 2 * BN * LDS_W;

    const int bm = blockIdx.y * BM;
    const int bn = blockIdx.x * BN;
    const int tid  = threadIdx.x;
    const int warp = tid >> 5;
    const int lane = tid & 31;
    const int wm = (warp & 3) * 32;      // warp M offset
    const int wn = (warp >> 2) * 64;     // warp N offset
    const int g  = lane >> 2;            // 0..7
    const int tg = lane & 3;             // 0..3

    const int lr = tid >> 3;             // 0..31
    const int lc = (tid & 7) * 4;        // 0,4,...,28

    float acc[2][8][4];
#pragma unroll
    for (int i = 0; i < 2; i++)
#pragma unroll
        for (int j = 0; j < 8; j++)
#pragma unroll
            for (int k = 0; k < 4; k++) acc[i][j][k] = 0.f;

    // store a float4 split into hi/lo smem
    auto stsplit = [&](uint32_t* Hs, uint32_t* Ls, int idx, float4 v) {
        uint32_t h0, l0, h1, l1, h2, l2, h3, l3;
        split_tf32(v.x, h0, l0); split_tf32(v.y, h1, l1);
        split_tf32(v.z, h2, l2); split_tf32(v.w, h3, l3);
        *(uint4*)&Hs[idx] = make_uint4(h0, h1, h2, h3);
        *(uint4*)&Ls[idx] = make_uint4(l0, l1, l2, l3);
    };

    // ---- prologue: tile 0 -> buffer 0
#pragma unroll
    for (int i = 0; i < 4; i++) {
        const int row = lr + i * 32;
        float4 va = *(const float4*)(A + (size_t)(bm + row) * K + lc);
        stsplit(AH, AL, row * LDS_W + lc, va);
        float4 vb = make_float4(0.f, 0.f, 0.f, 0.f);
        if (!NGUARD || (bn + row) < N)
            vb = *(const float4*)(Bm + (size_t)(bn + row) * K + lc);
        stsplit(BH, BL, row * LDS_W + lc, vb);
    }
    __syncthreads();

    const int nt = K / BK;
    for (int kt = 0; kt < nt; kt++) {
        const int cur = kt & 1;
        const bool pf = (kt + 1) < nt;
        float4 sa[4], sb[4];
        if (pf) {
            const int k0 = (kt + 1) * BK;
#pragma unroll
            for (int i = 0; i < 4; i++) {
                const int row = lr + i * 32;
                sa[i] = *(const float4*)(A + (size_t)(bm + row) * K + k0 + lc);
                if (!NGUARD || (bn + row) < N)
                    sb[i] = *(const float4*)(Bm + (size_t)(bn + row) * K + k0 + lc);
                else
                    sb[i] = make_float4(0.f, 0.f, 0.f, 0.f);
            }
        }

        const uint32_t* AHc = AH + cur * BM * LDS_W;
        const uint32_t* ALc = AL + cur * BM * LDS_W;
        const uint32_t* BHc = BH + cur * BN * LDS_W;
        const uint32_t* BLc = BL + cur * BN * LDS_W;

#pragma unroll
        for (int ks = 0; ks < 4; ks++) {
            const int kb = ks * 8;
            uint32_t ah[2][4], al[2][4];
#pragma unroll
            for (int mf = 0; mf < 2; mf++) {
                const int r = wm + mf * 16 + g;
                const int o0 = r * LDS_W + kb + tg;
                const int o1 = (r + 8) * LDS_W + kb + tg;
                ah[mf][0] = AHc[o0];     ah[mf][1] = AHc[o1];
                ah[mf][2] = AHc[o0 + 4]; ah[mf][3] = AHc[o1 + 4];
                al[mf][0] = ALc[o0];     al[mf][1] = ALc[o1];
                al[mf][2] = ALc[o0 + 4]; al[mf][3] = ALc[o1 + 4];
            }
#pragma unroll
            for (int nf = 0; nf < 8; nf++) {
                const int c = wn + nf * 8 + g;
                const int ob = c * LDS_W + kb + tg;
                const uint32_t bh0 = BHc[ob], bh1 = BHc[ob + 4];
                const uint32_t bl0 = BLc[ob], bl1 = BLc[ob + 4];
#pragma unroll
                for (int mf = 0; mf < 2; mf++) {
                    MMA_TF32(acc[mf][nf], al[mf][0], al[mf][1], al[mf][2], al[mf][3], bh0, bh1);
                    MMA_TF32(acc[mf][nf], ah[mf][0], ah[mf][1], ah[mf][2], ah[mf][3], bl0, bl1);
                    MMA_TF32(acc[mf][nf], ah[mf][0], ah[mf][1], ah[mf][2], ah[mf][3], bh0, bh1);
                }
            }
        }

        if (pf) {
            const int nxt = cur ^ 1;
#pragma unroll
            for (int i = 0; i < 4; i++) {
                const int row = lr + i * 32;
                stsplit(AH, AL, (nxt * BM + row) * LDS_W + lc, sa[i]);
                stsplit(BH, BL, (nxt * BN + row) * LDS_W + lc, sb[i]);
            }
        }
        __syncthreads();
    }

    // ---- epilogue: float2 stores
#pragma unroll
    for (int mf = 0; mf < 2; mf++) {
#pragma unroll
        for (int nf = 0; nf < 8; nf++) {
            const int row = bm + wm + mf * 16 + g;
            const int col = bn + wn + nf * 8 + tg * 2;
            if (!NGUARD || col < N) {
                *(float2*)(C + (size_t)row * N + col) =
                    make_float2(acc[mf][nf][0], acc[mf][nf][1]);
                *(float2*)(C + (size_t)(row + 8) * N + col) =
                    make_float2(acc[mf][nf][2], acc[mf][nf][3]);
            }
        }
    }
}

// ---------------------------------------------------------------------------
// h[m,s] = sum_r u[m,r] * (W[m, r*64+s] + bm[r*64+s])
// ---------------------------------------------------------------------------
__global__ __launch_bounds__(256)
void contract_k(const float* __restrict__ W, const float* __restrict__ u,
                const float* __restrict__ bm, float* __restrict__ h)
{
    __shared__ float sbm[NRR];
    __shared__ float su[4][NR];
    const int tid = threadIdx.x;
    const int m0  = blockIdx.x * 4;

    for (int i = tid; i < NRR; i += 256) sbm[i] = bm[i];
    {
        const int r = tid >> 6, c = tid & 63;
        su[r][c] = u[(size_t)(m0 + r) * NR + c];
    }
    __syncthreads();

    const int mi = tid >> 6;   // 0..3
    const int s  = tid & 63;
    const float* Wr = W + (size_t)(m0 + mi) * NRR;
    float acc = 0.f;
#pragma unroll
    for (int r = 0; r < NR; r++)
        acc += su[mi][r] * (Wr[r * NR + s] + sbm[r * NR + s]);
    h[(size_t)(m0 + mi) * NR + s] = acc;
}

// ---------------------------------------------------------------------------
// out[m,n] = act( sum_s h[m,s] * V[n,s] + bias[n] ),  out is [NB, ND]
// ---------------------------------------------------------------------------
template<bool RELU>
__global__ __launch_bounds__(256)
void vgemm_k(const float* __restrict__ h, const float* __restrict__ V,
             const float* __restrict__ bias, float* __restrict__ out)
{
    __shared__ float hs[64][65];
    __shared__ float vs[64][65];
    const int m0 = blockIdx.y * 64;
    const int n0 = blockIdx.x * 64;
    const int tid = threadIdx.x;

    {
        const int r = tid >> 2;
        const int c = (tid & 3) * 16;
        const float4* hp = (const float4*)(h + (size_t)(m0 + r) * NR + c);
        const float4* vp = (const float4*)(V + (size_t)(n0 + r) * NR + c);
#pragma unroll
        for (int j = 0; j < 4; j++) {
            float4 hv = hp[j];
            hs[r][c + 4 * j + 0] = hv.x; hs[r][c + 4 * j + 1] = hv.y;
            hs[r][c + 4 * j + 2] = hv.z; hs[r][c + 4 * j + 3] = hv.w;
            float4 vv = vp[j];
            vs[r][c + 4 * j + 0] = vv.x; vs[r][c + 4 * j + 1] = vv.y;
            vs[r][c + 4 * j + 2] = vv.z; vs[r][c + 4 * j + 3] = vv.w;
        }
    }
    __syncthreads();

    const int tm = (tid >> 4) * 4;
    const int tn = (tid & 15) * 4;
    float acc[4][4];
#pragma unroll
    for (int i = 0; i < 4; i++)
#pragma unroll
        for (int j = 0; j < 4; j++) acc[i][j] = 0.f;

#pragma unroll
    for (int s = 0; s < 64; s++) {
        float av[4], bv[4];
#pragma unroll
        for (int i = 0; i < 4; i++) av[i] = hs[tm + i][s];
#pragma unroll
        for (int j = 0; j < 4; j++) bv[j] = vs[tn + j][s];
#pragma unroll
        for (int i = 0; i < 4; i++)
#pragma unroll
            for (int j = 0; j < 4; j++) acc[i][j] += av[i] * bv[j];
    }

#pragma unroll
    for (int i = 0; i < 4; i++) {
#pragma unroll
        for (int j = 0; j < 4; j++) {
            float v = acc[i][j] + bias[n0 + tn + j];
            if (RELU) v = fmaxf(v, 0.f);
            out[(size_t)(m0 + tm + i) * ND + (n0 + tn + j)] = v;
        }
    }
}

// ---------------------------------------------------------------------------
extern "C" void kernel_launch(void* const* d_in, const int* in_sizes, int n_in,
                              void* d_out, int out_size)
{
    const float* x = (const float*)d_in[0];

    float *W, *u, *h, *a0, *a1;
    cudaGetSymbolAddress((void**)&W,  g_W);
    cudaGetSymbolAddress((void**)&u,  g_u);
    cudaGetSymbolAddress((void**)&h,  g_h);
    cudaGetSymbolAddress((void**)&a0, g_act0);
    cudaGetSymbolAddress((void**)&a1, g_act1);

    const int smem_bytes = 4 * (BM + BN) * LDS_W * (int)sizeof(uint32_t); // 147456
    cudaFuncSetAttribute(gemm_tn_3xtf32<false>,
                         cudaFuncAttributeMaxDynamicSharedMemorySize, smem_bytes);
    cudaFuncSetAttribute(gemm_tn_3xtf32<true>,
                         cudaFuncAttributeMaxDynamicSharedMemorySize, smem_bytes);

    const float* X = x;
    float* acts[2] = {a0, a1};

    for (int l = 0; l < 3; l++) {
        const float* Wm   = (const float*)d_in[1 + 5 * l + 0];
        const float* bm   = (const float*)d_in[1 + 5 * l + 1];
        const float* U    = (const float*)d_in[1 + 5 * l + 2];
        const float* V    = (const float*)d_in[1 + 5 * l + 3];
        const float* bias = (const float*)d_in[1 + 5 * l + 4];
        float* out = (l == 2) ? (float*)d_out : acts[l];

        // 1) per-sample weights: W = X @ Wm^T   [8192 x 4096]
        gemm_tn_3xtf32<false><<<dim3(NRR / BN, NB / BM), 256, smem_bytes>>>(
            X, Wm, W, NB, NRR, ND);
        // 2) u = X @ U^T   [8192 x 64]
        gemm_tn_3xtf32<true><<<dim3(1, NB / BM), 256, smem_bytes>>>(
            X, U, u, NB, NR, ND);
        // 3) h = einsum('br,brs->bs', u, W+bm)
        contract_k<<<NB / 4, 256>>>(W, u, bm, h);
        // 4) out = act(h @ V^T + b)
        if (l < 2)
            vgemm_k<true><<<dim3(ND / 64, NB / 64), 256>>>(h, V, bias, out);
        else
            vgemm_k<false><<<dim3(ND / 64, NB / 64), 256>>>(h, V, bias, out);

        X = out;
    }
}

// round 9
// speedup vs baseline: 1.7526x; 1.7526x over previous
#include <cuda_runtime.h>
#include <cuda_bf16.h>
#include <cstdint>

// ---------------- problem constants ----------------
#define NB   8192
#define ND   1024
#define NR   64
#define NRR  4096

// ---------------- GEMM tiling ----------------
#define GBM 128              // CTA M tile
#define GBN 128              // CTA N tile
#define NT_W (NRR / GBN)     // 32 N-tiles for W gemm
#define BKE  64              // bf16 K elems per stage (32 u32 per row)
#define NCH  (ND / BKE)      // 16 K-stages
#define LDS_W 36             // u32 row stride (32 + 4 skew)
#define MAT_BYTES (GBM * LDS_W * 4)          // 18432 per matrix tile
#define STAGE_BYTES (4 * MAT_BYTES)          // Ahi,Alo,Bhi,Blo = 73728
#define DSMEM_REQ (2 * STAGE_BYTES)          // 147456

// ---------------- static device scratch ----------------
__device__ __nv_bfloat16 g_xhi[(size_t)NB * ND];
__device__ __nv_bfloat16 g_xlo[(size_t)NB * ND];
__device__ __nv_bfloat16 g_whi[(size_t)NRR * ND];
__device__ __nv_bfloat16 g_wlo[(size_t)NRR * ND];
__device__ __nv_bfloat16 g_uhi[(size_t)GBM * ND];   // U padded to 128 rows
__device__ __nv_bfloat16 g_ulo[(size_t)GBM * ND];
__device__ float g_u [(size_t)NB * NR];
__device__ float g_hp[(size_t)NB * NT_W * NR];      // 32-way partials of h (64MB)
__device__ float g_h [(size_t)NB * NR];

// ---------------- helpers ----------------
__device__ __forceinline__ uint32_t smem_u32(const void* p) {
    uint32_t a;
    asm("{ .reg .u64 t; cvta.to.shared.u64 t, %1; cvt.u32.u64 %0, t; }"
        : "=r"(a) : "l"(p));
    return a;
}
__device__ __forceinline__ void cpa16(uint32_t s, const void* g) {
    asm volatile("cp.async.cg.shared.global [%0], [%1], 16;\n" :: "r"(s), "l"(g));
}
#define CP_COMMIT() asm volatile("cp.async.commit_group;\n" ::: "memory")
#define CP_WAIT(n)  asm volatile("cp.async.wait_group %0;\n" :: "n"(n) : "memory")

#define MMA_BF16(acc, a0, a1, a2, a3, b0, b1)                                  \
    asm("mma.sync.aligned.m16n8k16.row.col.f32.bf16.bf16.f32 "                 \
        "{%0,%1,%2,%3}, {%4,%5,%6,%7}, {%8,%9}, {%0,%1,%2,%3};\n"              \
        : "+f"(acc[0]), "+f"(acc[1]), "+f"(acc[2]), "+f"(acc[3])               \
        : "r"(a0), "r"(a1), "r"(a2), "r"(a3), "r"(b0), "r"(b1))

// ---------------------------------------------------------------------------
// 3xBF16 mma.sync GEMM:  D[128 x 128] = A[128 x 1024] @ B[128 x 1024]^T
// Operands pre-split hi/lo bf16; per k-step: ahi*bhi + ahi*blo + alo*bhi.
// CTA 128x128, 8 warps (4x2), warp tile 32x64, cp.async 2-stage pipeline.
// MODE 0: u-gemm (B = padded U): store D cols [0,64) to out = u [NB x 64].
// MODE 1: W-gen + fused contract: this CTA's N-tile covers r-blocks
//         j = nt*2, nt*2+1; emits hp[m][nt][s] = sum_j u[m,nt*2+j]*(D+bm).
// ---------------------------------------------------------------------------
template<int MODE>
__global__ __launch_bounds__(256)
void gemm3bf16(const __nv_bfloat16* __restrict__ Ahi_g, const __nv_bfloat16* __restrict__ Alo_g,
               const __nv_bfloat16* __restrict__ Bhi_g, const __nv_bfloat16* __restrict__ Blo_g,
               const float* __restrict__ uvec, const float* __restrict__ bmvec,
               float* __restrict__ out)
{
    extern __shared__ char dynsmem[];
    __shared__ float sbm[GBN];

    uint32_t* su = (uint32_t*)dynsmem;            // u32 view of operand smem
    const uint32_t sbase = smem_u32(dynsmem);

    const int tid  = threadIdx.x;
    const int warp = tid >> 5;
    const int lane = tid & 31;
    const int wm = (warp & 3) * 32;               // warp M offset
    const int wn = (warp >> 2) * 64;              // warp N offset
    const int g  = lane >> 2;                     // 0..7
    const int tg = lane & 3;                      // 0..3

    const int nt = blockIdx.x;
    const int mt = blockIdx.y;
    const size_t arow0 = (size_t)mt * GBM;
    const size_t brow0 = (size_t)nt * GBN;

    if (MODE == 1 && tid < GBN) sbm[tid] = bmvec[nt * GBN + tid];

    float acc[2][8][4];
#pragma unroll
    for (int i = 0; i < 2; i++)
#pragma unroll
        for (int j = 0; j < 8; j++)
#pragma unroll
            for (int k = 0; k < 4; k++) acc[i][j][k] = 0.f;

    // ---- stage loader: 4 matrices x 128 rows x 8 x16B; 16 cp.async/thread ----
    auto load_stage = [&](int stage, int buf) {
        const uint32_t base = sbase + buf * STAGE_BYTES;
        const int k0 = stage * BKE;
#pragma unroll
        for (int it = 0; it < 4; it++) {
            const int t = tid + it * 256;         // 0..1023
            const int row = t >> 3, c = t & 7;
            const uint32_t so = (uint32_t)(row * (LDS_W * 4) + c * 16);
            const size_t ga = (arow0 + row) * ND + k0 + c * 8;
            const size_t gb = (brow0 + row) * ND + k0 + c * 8;
            cpa16(base + so,                 Ahi_g + ga);
            cpa16(base + MAT_BYTES + so,     Alo_g + ga);
            cpa16(base + 2 * MAT_BYTES + so, Bhi_g + gb);
            cpa16(base + 3 * MAT_BYTES + so, Blo_g + gb);
        }
        CP_COMMIT();
    };

    load_stage(0, 0);

    for (int i = 0; i < NCH; i++) {
        if (i + 1 < NCH) {
            load_stage(i + 1, (i + 1) & 1);
            CP_WAIT(1);
        } else {
            CP_WAIT(0);
        }
        __syncthreads();                          // stage i resident

        const uint32_t* AH = su + (i & 1) * (STAGE_BYTES / 4);
        const uint32_t* AL = AH + MAT_BYTES / 4;
        const uint32_t* BH = AL + MAT_BYTES / 4;
        const uint32_t* BL = BH + MAT_BYTES / 4;

#pragma unroll
        for (int ks = 0; ks < 4; ks++) {
            const int kb = ks * 8;
            uint32_t ah[2][4], al[2][4];
#pragma unroll
            for (int mf = 0; mf < 2; mf++) {
                const int r = wm + mf * 16 + g;
                const int o0 = r * LDS_W + kb + tg;
                const int o1 = (r + 8) * LDS_W + kb + tg;
                ah[mf][0] = AH[o0];     ah[mf][1] = AH[o1];
                ah[mf][2] = AH[o0 + 4]; ah[mf][3] = AH[o1 + 4];
                al[mf][0] = AL[o0];     al[mf][1] = AL[o1];
                al[mf][2] = AL[o0 + 4]; al[mf][3] = AL[o1 + 4];
            }
#pragma unroll
            for (int nf = 0; nf < 8; nf++) {
                const int c = wn + nf * 8 + g;
                const int ob = c * LDS_W + kb + tg;
                const uint32_t bh0 = BH[ob], bh1 = BH[ob + 4];
                const uint32_t bl0 = BL[ob], bl1 = BL[ob + 4];
#pragma unroll
                for (int mf = 0; mf < 2; mf++) {
                    MMA_BF16(acc[mf][nf], ah[mf][0], ah[mf][1], ah[mf][2], ah[mf][3], bh0, bh1);
                    MMA_BF16(acc[mf][nf], ah[mf][0], ah[mf][1], ah[mf][2], ah[mf][3], bl0, bl1);
                    MMA_BF16(acc[mf][nf], al[mf][0], al[mf][1], al[mf][2], al[mf][3], bh0, bh1);
                }
            }
        }
        __syncthreads();                          // all reads of buf done
    }

    if (MODE == 0) {
        // store cols [0,64): only wn==0 warps hold them
        if (wn == 0) {
#pragma unroll
            for (int mf = 0; mf < 2; mf++) {
#pragma unroll
                for (int nf = 0; nf < 8; nf++) {
                    const size_t row = arow0 + wm + mf * 16 + g;
                    const int col = nf * 8 + tg * 2;
                    *(float2*)(out + row * NR + col) =
                        make_float2(acc[mf][nf][0], acc[mf][nf][1]);
                    *(float2*)(out + (row + 8) * NR + col) =
                        make_float2(acc[mf][nf][2], acc[mf][nf][3]);
                }
            }
        }
        return;
    }

    // ---- MODE 1: fused contract. part[128][65] fp32 reuses operand smem ----
    float* part = (float*)dynsmem;
    for (int idx = tid; idx < 128 * 65; idx += 256) part[idx] = 0.f;
    __syncthreads();

    const int j = warp >> 2;                      // r-block within tile (0/1)
    float um[4];
#pragma unroll
    for (int mf = 0; mf < 2; mf++) {
        um[mf * 2 + 0] = uvec[(arow0 + wm + mf * 16 + g) * NR + nt * 2 + j];
        um[mf * 2 + 1] = uvec[(arow0 + wm + mf * 16 + 8 + g) * NR + nt * 2 + j];
    }

    // two phases so the two r-blocks never race on part[] (deterministic)
#pragma unroll
    for (int ph = 0; ph < 2; ph++) {
        if (j == ph) {
#pragma unroll
            for (int mf = 0; mf < 2; mf++) {
                const int r0 = wm + mf * 16 + g;
#pragma unroll
                for (int nf = 0; nf < 8; nf++) {
                    const int s0 = nf * 8 + tg * 2;
                    const float b0 = sbm[j * 64 + s0];
                    const float b1 = sbm[j * 64 + s0 + 1];
                    part[r0 * 65 + s0]           += um[mf * 2] * (acc[mf][nf][0] + b0);
                    part[r0 * 65 + s0 + 1]       += um[mf * 2] * (acc[mf][nf][1] + b1);
                    part[(r0 + 8) * 65 + s0]     += um[mf * 2 + 1] * (acc[mf][nf][2] + b0);
                    part[(r0 + 8) * 65 + s0 + 1] += um[mf * 2 + 1] * (acc[mf][nf][3] + b1);
                }
            }
        }
        __syncthreads();
    }

    // store hp[m][nt][s]
    for (int idx = tid; idx < 128 * 64; idx += 256) {
        const int row = idx >> 6, s = idx & 63;
        out[((arow0 + row) * NT_W + nt) * NR + s] = part[row * 65 + s];
    }
}

// ---------------------------------------------------------------------------
// h[m,s] = sum_t hp[m,t,s]
// ---------------------------------------------------------------------------
__global__ __launch_bounds__(256)
void reduce_h(const float* __restrict__ hp, float* __restrict__ h)
{
    const int idx = blockIdx.x * 256 + threadIdx.x;   // over NB*NR
    const int m = idx >> 6, s = idx & 63;
    const float* p = hp + (size_t)m * (NT_W * NR) + s;
    float a = 0.f;
#pragma unroll
    for (int t = 0; t < NT_W; t++) a += p[t * NR];
    h[idx] = a;
}

// ---------------------------------------------------------------------------
// out[m,n] = act( sum_s h[m,s] * V[n,s] + bias[n] )
// BF16OUT: emit hi/lo bf16 split directly (feeds next layer's GEMM)
// ---------------------------------------------------------------------------
template<bool RELU, bool BF16OUT>
__global__ __launch_bounds__(256)
void vgemm_k(const float* __restrict__ h, const float* __restrict__ V,
             const float* __restrict__ bias, float* __restrict__ out,
             __nv_bfloat16* __restrict__ ohi, __nv_bfloat16* __restrict__ olo)
{
    __shared__ float hs[64][65];
    __shared__ float vs[64][65];
    const int m0 = blockIdx.y * 64;
    const int n0 = blockIdx.x * 64;
    const int tid = threadIdx.x;

    {
        const int r = tid >> 2;
        const int c = (tid & 3) * 16;
        const float4* hp = (const float4*)(h + (size_t)(m0 + r) * NR + c);
        const float4* vp = (const float4*)(V + (size_t)(n0 + r) * NR + c);
#pragma unroll
        for (int j = 0; j < 4; j++) {
            float4 hv = hp[j];
            hs[r][c + 4 * j + 0] = hv.x; hs[r][c + 4 * j + 1] = hv.y;
            hs[r][c + 4 * j + 2] = hv.z; hs[r][c + 4 * j + 3] = hv.w;
            float4 vv = vp[j];
            vs[r][c + 4 * j + 0] = vv.x; vs[r][c + 4 * j + 1] = vv.y;
            vs[r][c + 4 * j + 2] = vv.z; vs[r][c + 4 * j + 3] = vv.w;
        }
    }
    __syncthreads();

    const int tm = (tid >> 4) * 4;
    const int tn = (tid & 15) * 4;
    float acc[4][4];
#pragma unroll
    for (int i = 0; i < 4; i++)
#pragma unroll
        for (int j = 0; j < 4; j++) acc[i][j] = 0.f;

#pragma unroll
    for (int s = 0; s < 64; s++) {
        float av[4], bv[4];
#pragma unroll
        for (int i = 0; i < 4; i++) av[i] = hs[tm + i][s];
#pragma unroll
        for (int j = 0; j < 4; j++) bv[j] = vs[tn + j][s];
#pragma unroll
        for (int i = 0; i < 4; i++)
#pragma unroll
            for (int j = 0; j < 4; j++) acc[i][j] += av[i] * bv[j];
    }

#pragma unroll
    for (int i = 0; i < 4; i++) {
        float v[4];
#pragma unroll
        for (int j = 0; j < 4; j++) {
            v[j] = acc[i][j] + bias[n0 + tn + j];
            if (RELU) v[j] = fmaxf(v[j], 0.f);
        }
        const size_t o = (size_t)(m0 + tm + i) * ND + (n0 + tn);
        if (BF16OUT) {
            __nv_bfloat16 hh[4], ll[4];
#pragma unroll
            for (int j = 0; j < 4; j++) {
                hh[j] = __float2bfloat16_rn(v[j]);
                ll[j] = __float2bfloat16_rn(v[j] - __bfloat162float(hh[j]));
            }
            *(__nv_bfloat162*)(ohi + o)     = __halves2bfloat162(hh[0], hh[1]);
            *(__nv_bfloat162*)(ohi + o + 2) = __halves2bfloat162(hh[2], hh[3]);
            *(__nv_bfloat162*)(olo + o)     = __halves2bfloat162(ll[0], ll[1]);
            *(__nv_bfloat162*)(olo + o + 2) = __halves2bfloat162(ll[2], ll[3]);
        } else {
            *(float4*)(out + o) = make_float4(v[0], v[1], v[2], v[3]);
        }
    }
}

// ---------------------------------------------------------------------------
// fp32 -> bf16 hi/lo split (elementwise, float4 vectorized)
// ---------------------------------------------------------------------------
__global__ __launch_bounds__(256)
void conv_split(const float4* __restrict__ in, __nv_bfloat162* __restrict__ hi,
                __nv_bfloat162* __restrict__ lo, int n4)
{
    const int i = blockIdx.x * 256 + threadIdx.x;
    if (i >= n4) return;
    const float4 v = in[i];
    float f[4] = {v.x, v.y, v.z, v.w};
    __nv_bfloat16 hh[4], ll[4];
#pragma unroll
    for (int j = 0; j < 4; j++) {
        hh[j] = __float2bfloat16_rn(f[j]);
        ll[j] = __float2bfloat16_rn(f[j] - __bfloat162float(hh[j]));
    }
    hi[2 * i]     = __halves2bfloat162(hh[0], hh[1]);
    hi[2 * i + 1] = __halves2bfloat162(hh[2], hh[3]);
    lo[2 * i]     = __halves2bfloat162(ll[0], ll[1]);
    lo[2 * i + 1] = __halves2bfloat162(ll[2], ll[3]);
}

// U [64 x 1024] -> padded [128 x 1024] hi/lo with zero rows 64..127
__global__ __launch_bounds__(256)
void conv_upad(const float* __restrict__ U, __nv_bfloat162* __restrict__ hi,
               __nv_bfloat162* __restrict__ lo)
{
    const int i = blockIdx.x * 256 + threadIdx.x;   // over 128*1024/4 groups
    if (i >= GBM * ND / 4) return;
    const int row = (i * 4) >> 10;
    float4 v = make_float4(0.f, 0.f, 0.f, 0.f);
    if (row < NR) v = ((const float4*)U)[i];
    float f[4] = {v.x, v.y, v.z, v.w};
    __nv_bfloat16 hh[4], ll[4];
#pragma unroll
    for (int j = 0; j < 4; j++) {
        hh[j] = __float2bfloat16_rn(f[j]);
        ll[j] = __float2bfloat16_rn(f[j] - __bfloat162float(hh[j]));
    }
    hi[2 * i]     = __halves2bfloat162(hh[0], hh[1]);
    hi[2 * i + 1] = __halves2bfloat162(hh[2], hh[3]);
    lo[2 * i]     = __halves2bfloat162(ll[0], ll[1]);
    lo[2 * i + 1] = __halves2bfloat162(ll[2], ll[3]);
}

// ---------------------------------------------------------------------------
extern "C" void kernel_launch(void* const* d_in, const int* in_sizes, int n_in,
                              void* d_out, int out_size)
{
    const float* x = (const float*)d_in[0];

    __nv_bfloat16 *xhi, *xlo, *whi, *wlo, *uhi, *ulo;
    float *u, *hp, *h;
    cudaGetSymbolAddress((void**)&xhi, g_xhi);
    cudaGetSymbolAddress((void**)&xlo, g_xlo);
    cudaGetSymbolAddress((void**)&whi, g_whi);
    cudaGetSymbolAddress((void**)&wlo, g_wlo);
    cudaGetSymbolAddress((void**)&uhi, g_uhi);
    cudaGetSymbolAddress((void**)&ulo, g_ulo);
    cudaGetSymbolAddress((void**)&u,  g_u);
    cudaGetSymbolAddress((void**)&hp, g_hp);
    cudaGetSymbolAddress((void**)&h,  g_h);

    cudaFuncSetAttribute(gemm3bf16<0>, cudaFuncAttributeMaxDynamicSharedMemorySize, DSMEM_REQ);
    cudaFuncSetAttribute(gemm3bf16<1>, cudaFuncAttributeMaxDynamicSharedMemorySize, DSMEM_REQ);

    // split layer-0 input
    conv_split<<<(NB * ND / 4 + 255) / 256, 256>>>(
        (const float4*)x, (__nv_bfloat162*)xhi, (__nv_bfloat162*)xlo, NB * ND / 4);

    for (int l = 0; l < 3; l++) {
        const float* Wm   = (const float*)d_in[1 + 5 * l + 0];
        const float* bm   = (const float*)d_in[1 + 5 * l + 1];
        const float* U    = (const float*)d_in[1 + 5 * l + 2];
        const float* V    = (const float*)d_in[1 + 5 * l + 3];
        const float* bias = (const float*)d_in[1 + 5 * l + 4];

        // split weights
        conv_split<<<(NRR * ND / 4 + 255) / 256, 256>>>(
            (const float4*)Wm, (__nv_bfloat162*)whi, (__nv_bfloat162*)wlo, NRR * ND / 4);
        conv_upad<<<(GBM * ND / 4 + 255) / 256, 256>>>(
            U, (__nv_bfloat162*)uhi, (__nv_bfloat162*)ulo);

        // u = X @ U^T
        gemm3bf16<0><<<dim3(1, NB / GBM), 256, DSMEM_REQ>>>(
            xhi, xlo, uhi, ulo, nullptr, nullptr, u);

        // W-gen GEMM + fused contract -> 32-way partials of h
        gemm3bf16<1><<<dim3(NT_W, NB / GBM), 256, DSMEM_REQ>>>(
            xhi, xlo, whi, wlo, u, bm, hp);

        reduce_h<<<NB * NR / 256, 256>>>(hp, h);

        // out = act(h @ V^T + b); layers 0,1 emit bf16 hi/lo for next GEMM
        if (l < 2)
            vgemm_k<true, true><<<dim3(ND / 64, NB / 64), 256>>>(
                h, V, bias, nullptr, xhi, xlo);
        else
            vgemm_k<false, false><<<dim3(ND / 64, NB / 64), 256>>>(
                h, V, bias, (float*)d_out, nullptr, nullptr);
    }
}

// round 10
// speedup vs baseline: 1.7805x; 1.0160x over previous
#include <cuda_runtime.h>
#include <cuda_bf16.h>
#include <cstdint>

// ---------------- problem constants ----------------
#define NB   8192
#define ND   1024
#define NR   64
#define NRR  4096

// ---------------- GEMM tiling ----------------
#define GBM 128              // CTA M tile
#define GBN 128              // CTA N tile
#define NT_W (NRR / GBN)     // 32 N-tiles for W gemm
#define BKE  64              // bf16 K elems per stage (32 u32 per row)
#define LDS_W 36             // u32 row stride (32 + 4 skew)
#define MAT_BYTES (GBM * LDS_W * 4)          // 18432 per matrix tile
#define STAGE_BYTES (4 * MAT_BYTES)          // Ahi,Alo,Bhi,Blo = 73728
#define DSMEM_REQ (2 * STAGE_BYTES)          // 147456

// ---------------- static device scratch ----------------
__device__ __nv_bfloat16 g_xhi[(size_t)NB * ND];
__device__ __nv_bfloat16 g_xlo[(size_t)NB * ND];
__device__ __nv_bfloat16 g_whi[(size_t)NRR * ND];
__device__ __nv_bfloat16 g_wlo[(size_t)NRR * ND];
__device__ __nv_bfloat16 g_uhi[(size_t)GBM * ND];   // U padded to 128 rows
__device__ __nv_bfloat16 g_ulo[(size_t)GBM * ND];
__device__ float g_u2[(size_t)2 * NB * NR];         // 2 K-slice partials of u
__device__ float g_hp[(size_t)NB * NT_W * NR];      // 32-way partials of h
__device__ float g_h [(size_t)NB * NR];

// ---------------- helpers ----------------
__device__ __forceinline__ uint32_t smem_u32(const void* p) {
    uint32_t a;
    asm("{ .reg .u64 t; cvta.to.shared.u64 t, %1; cvt.u32.u64 %0, t; }"
        : "=r"(a) : "l"(p));
    return a;
}
__device__ __forceinline__ void cpa16(uint32_t s, const void* g) {
    asm volatile("cp.async.cg.shared.global [%0], [%1], 16;\n" :: "r"(s), "l"(g));
}
#define CP_COMMIT() asm volatile("cp.async.commit_group;\n" ::: "memory")
#define CP_WAIT(n)  asm volatile("cp.async.wait_group %0;\n" :: "n"(n) : "memory")

#define MMA_BF16(acc, a0, a1, a2, a3, b0, b1)                                  \
    asm("mma.sync.aligned.m16n8k16.row.col.f32.bf16.bf16.f32 "                 \
        "{%0,%1,%2,%3}, {%4,%5,%6,%7}, {%8,%9}, {%0,%1,%2,%3};\n"              \
        : "+f"(acc[0]), "+f"(acc[1]), "+f"(acc[2]), "+f"(acc[3])               \
        : "r"(a0), "r"(a1), "r"(a2), "r"(a3), "r"(b0), "r"(b1))

#define LDSM_X4(r, addr)                                                       \
    asm volatile("ldmatrix.sync.aligned.m8n8.x4.shared.b16 {%0,%1,%2,%3}, [%4];" \
        : "=r"((r)[0]), "=r"((r)[1]), "=r"((r)[2]), "=r"((r)[3]) : "r"(addr))

// ---------------------------------------------------------------------------
// 3xBF16 mma.sync GEMM:  D[128 x 128] = A[128 x K] @ B[128 x K]^T
// ldmatrix.x4 fragment loads; 3 ILP passes per k-step: hi*hi, hi*lo, lo*hi.
// MODE 0: u-gemm, K-split: blockIdx.x = K-slice (0/1), each does K/2=512;
//         stores D cols [0,64) to out + slice*NB*NR.
// MODE 1: W-gen + fused contract: blockIdx.x = N-tile nt; emits
//         hp[m][nt][s] = sum_j u[m, nt*2+j] * (D[m, j*64+s] + bm[...]),
//         where u[m,r] = uvec[m*NR+r] + uvec[NB*NR + m*NR+r].
// ---------------------------------------------------------------------------
template<int MODE>
__global__ __launch_bounds__(256)
void gemm3bf16(const __nv_bfloat16* __restrict__ Ahi_g, const __nv_bfloat16* __restrict__ Alo_g,
               const __nv_bfloat16* __restrict__ Bhi_g, const __nv_bfloat16* __restrict__ Blo_g,
               const float* __restrict__ uvec, const float* __restrict__ bmvec,
               float* __restrict__ out)
{
    extern __shared__ char dynsmem[];
    __shared__ float sbm[GBN];

    const uint32_t sbase = smem_u32(dynsmem);

    const int tid  = threadIdx.x;
    const int warp = tid >> 5;
    const int lane = tid & 31;
    const int wm = (warp & 3) * 32;               // warp M offset
    const int wn = (warp >> 2) * 64;              // warp N offset
    const int g  = lane >> 2;                     // 0..7
    const int tg = lane & 3;                      // 0..3

    const int nt = blockIdx.x;
    const int mt = blockIdx.y;
    const size_t arow0 = (size_t)mt * GBM;
    const size_t brow0 = (MODE == 0) ? 0 : (size_t)nt * GBN;
    const int kbase = (MODE == 0) ? nt * (ND / 2) : 0;
    const int nst   = (MODE == 0) ? (ND / 2) / BKE : ND / BKE;

    if (MODE == 1 && tid < GBN) sbm[tid] = bmvec[nt * GBN + tid];

    float acc[2][8][4];
#pragma unroll
    for (int i = 0; i < 2; i++)
#pragma unroll
        for (int j = 0; j < 8; j++)
#pragma unroll
            for (int k = 0; k < 4; k++) acc[i][j][k] = 0.f;

    // ---- per-lane ldmatrix byte offsets (within a matrix area) ----
    // A x4: lanes 0-7 m0 (rows+0..7, col 0), 8-15 m1 (rows+8, col 0),
    //       16-23 m2 (rows+0..7, col+4), 24-31 m3 (rows+8, col+4)
    const int l8 = lane & 7;
    uint32_t aOffB[2], bOffB[4];
#pragma unroll
    for (int mf = 0; mf < 2; mf++)
        aOffB[mf] = (uint32_t)(((wm + mf * 16 + l8 + ((lane >> 3) & 1) * 8) * LDS_W
                                + (lane >> 4) * 4) * 4);
    // B x4 for nf-pair p: m0 (n+0..7, col0)->b[2p][0], m1 (n+0..7, col+4)->b[2p][1],
    //                     m2 (n+8..15, col0)->b[2p+1][0], m3 -> b[2p+1][1]
#pragma unroll
    for (int p = 0; p < 4; p++)
        bOffB[p] = (uint32_t)(((wn + p * 16 + l8 + ((lane >> 4) & 1) * 8) * LDS_W
                               + ((lane >> 3) & 1) * 4) * 4);

    // ---- stage loader: 4 matrices x 128 rows x 8 x16B; 16 cp.async/thread ----
    auto load_stage = [&](int stage, int buf) {
        const uint32_t base = sbase + buf * STAGE_BYTES;
        const int k0 = kbase + stage * BKE;
#pragma unroll
        for (int it = 0; it < 4; it++) {
            const int t = tid + it * 256;         // 0..1023
            const int row = t >> 3, c = t & 7;
            const uint32_t so = (uint32_t)(row * (LDS_W * 4) + c * 16);
            const size_t ga = (arow0 + row) * ND + k0 + c * 8;
            const size_t gb = (brow0 + row) * ND + k0 + c * 8;
            cpa16(base + so,                 Ahi_g + ga);
            cpa16(base + MAT_BYTES + so,     Alo_g + ga);
            cpa16(base + 2 * MAT_BYTES + so, Bhi_g + gb);
            cpa16(base + 3 * MAT_BYTES + so, Blo_g + gb);
        }
        CP_COMMIT();
    };

    load_stage(0, 0);

    for (int i = 0; i < nst; i++) {
        if (i + 1 < nst) {
            load_stage(i + 1, (i + 1) & 1);
            CP_WAIT(1);
        } else {
            CP_WAIT(0);
        }
        __syncthreads();                          // stage i resident

        const uint32_t stb = sbase + (i & 1) * STAGE_BYTES;

#pragma unroll
        for (int ks = 0; ks < 4; ks++) {
            const uint32_t kob = (uint32_t)(ks * 32);   // 8 u32 = 32 bytes
            uint32_t ah[2][4], al[2][4], bh[4][4], bl[4][4];
#pragma unroll
            for (int mf = 0; mf < 2; mf++) {
                LDSM_X4(ah[mf], stb + aOffB[mf] + kob);
                LDSM_X4(al[mf], stb + MAT_BYTES + aOffB[mf] + kob);
            }
#pragma unroll
            for (int p = 0; p < 4; p++) {
                LDSM_X4(bh[p], stb + 2 * MAT_BYTES + bOffB[p] + kob);
                LDSM_X4(bl[p], stb + 3 * MAT_BYTES + bOffB[p] + kob);
            }
            // pass 1: hi*hi  (16 independent MMAs)
#pragma unroll
            for (int p = 0; p < 4; p++)
#pragma unroll
                for (int mf = 0; mf < 2; mf++) {
                    MMA_BF16(acc[mf][2 * p],     ah[mf][0], ah[mf][1], ah[mf][2], ah[mf][3], bh[p][0], bh[p][1]);
                    MMA_BF16(acc[mf][2 * p + 1], ah[mf][0], ah[mf][1], ah[mf][2], ah[mf][3], bh[p][2], bh[p][3]);
                }
            // pass 2: hi*lo
#pragma unroll
            for (int p = 0; p < 4; p++)
#pragma unroll
                for (int mf = 0; mf < 2; mf++) {
                    MMA_BF16(acc[mf][2 * p],     ah[mf][0], ah[mf][1], ah[mf][2], ah[mf][3], bl[p][0], bl[p][1]);
                    MMA_BF16(acc[mf][2 * p + 1], ah[mf][0], ah[mf][1], ah[mf][2], ah[mf][3], bl[p][2], bl[p][3]);
                }
            // pass 3: lo*hi
#pragma unroll
            for (int p = 0; p < 4; p++)
#pragma unroll
                for (int mf = 0; mf < 2; mf++) {
                    MMA_BF16(acc[mf][2 * p],     al[mf][0], al[mf][1], al[mf][2], al[mf][3], bh[p][0], bh[p][1]);
                    MMA_BF16(acc[mf][2 * p + 1], al[mf][0], al[mf][1], al[mf][2], al[mf][3], bh[p][2], bh[p][3]);
                }
        }
        __syncthreads();                          // all reads of buf done
    }

    if (MODE == 0) {
        // store cols [0,64) of D to u partial slice nt
        float* o = out + (size_t)nt * NB * NR;
        if (wn == 0) {
#pragma unroll
            for (int mf = 0; mf < 2; mf++) {
#pragma unroll
                for (int nf = 0; nf < 8; nf++) {
                    const size_t row = arow0 + wm + mf * 16 + g;
                    const int col = nf * 8 + tg * 2;
                    *(float2*)(o + row * NR + col) =
                        make_float2(acc[mf][nf][0], acc[mf][nf][1]);
                    *(float2*)(o + (row + 8) * NR + col) =
                        make_float2(acc[mf][nf][2], acc[mf][nf][3]);
                }
            }
        }
        return;
    }

    // ---- MODE 1: fused contract. part[128][65] fp32 reuses operand smem ----
    float* part = (float*)dynsmem;
    for (int idx = tid; idx < 128 * 65; idx += 256) part[idx] = 0.f;
    __syncthreads();

    const int j = warp >> 2;                      // r-block within tile (0/1)
    const int ridx = nt * 2 + j;
    float um[4];
#pragma unroll
    for (int mf = 0; mf < 2; mf++) {
        const size_t r0 = (arow0 + wm + mf * 16 + g) * NR + ridx;
        const size_t r1 = (arow0 + wm + mf * 16 + 8 + g) * NR + ridx;
        um[mf * 2 + 0] = uvec[r0] + uvec[(size_t)NB * NR + r0];
        um[mf * 2 + 1] = uvec[r1] + uvec[(size_t)NB * NR + r1];
    }

    // two phases so the two r-blocks never race on part[] (deterministic)
#pragma unroll
    for (int ph = 0; ph < 2; ph++) {
        if (j == ph) {
#pragma unroll
            for (int mf = 0; mf < 2; mf++) {
                const int r0 = wm + mf * 16 + g;
#pragma unroll
                for (int nf = 0; nf < 8; nf++) {
                    const int s0 = nf * 8 + tg * 2;
                    const float b0 = sbm[j * 64 + s0];
                    const float b1 = sbm[j * 64 + s0 + 1];
                    part[r0 * 65 + s0]           += um[mf * 2] * (acc[mf][nf][0] + b0);
                    part[r0 * 65 + s0 + 1]       += um[mf * 2] * (acc[mf][nf][1] + b1);
                    part[(r0 + 8) * 65 + s0]     += um[mf * 2 + 1] * (acc[mf][nf][2] + b0);
                    part[(r0 + 8) * 65 + s0 + 1] += um[mf * 2 + 1] * (acc[mf][nf][3] + b1);
                }
            }
        }
        __syncthreads();
    }

    // store hp[m][nt][s]
    for (int idx = tid; idx < 128 * 64; idx += 256) {
        const int row = idx >> 6, s = idx & 63;
        out[((arow0 + row) * NT_W + nt) * NR + s] = part[row * 65 + s];
    }
}

// ---------------------------------------------------------------------------
// h[m,s] = sum_t hp[m,t,s]
// ---------------------------------------------------------------------------
__global__ __launch_bounds__(256)
void reduce_h(const float* __restrict__ hp, float* __restrict__ h)
{
    const int idx = blockIdx.x * 256 + threadIdx.x;   // over NB*NR
    const int m = idx >> 6, s = idx & 63;
    const float* p = hp + (size_t)m * (NT_W * NR) + s;
    float a = 0.f;
#pragma unroll
    for (int t = 0; t < NT_W; t++) a += p[t * NR];
    h[idx] = a;
}

// ---------------------------------------------------------------------------
// out[m,n] = act( sum_s h[m,s] * V[n,s] + bias[n] )
// Transposed smem ([s][m] / [s][n], stride 68) -> float4 inner-loop reads.
// BF16OUT: emit hi/lo bf16 split directly (feeds next layer's GEMM)
// ---------------------------------------------------------------------------
template<bool RELU, bool BF16OUT>
__global__ __launch_bounds__(256)
void vgemm_k(const float* __restrict__ h, const float* __restrict__ V,
             const float* __restrict__ bias, float* __restrict__ out,
             __nv_bfloat16* __restrict__ ohi, __nv_bfloat16* __restrict__ olo)
{
    __shared__ float hsT[64][68];   // [s][m]
    __shared__ float vsT[64][68];   // [s][n]
    const int m0 = blockIdx.y * 64;
    const int n0 = blockIdx.x * 64;
    const int tid = threadIdx.x;

    {
        const int r = tid >> 2;          // 0..63
        const int c = (tid & 3) * 16;    // 0,16,32,48
        const float4* hp = (const float4*)(h + (size_t)(m0 + r) * NR + c);
        const float4* vp = (const float4*)(V + (size_t)(n0 + r) * NR + c);
#pragma unroll
        for (int j = 0; j < 4; j++) {
            float4 hv = hp[j];
            hsT[c + 4 * j + 0][r] = hv.x; hsT[c + 4 * j + 1][r] = hv.y;
            hsT[c + 4 * j + 2][r] = hv.z; hsT[c + 4 * j + 3][r] = hv.w;
            float4 vv = vp[j];
            vsT[c + 4 * j + 0][r] = vv.x; vsT[c + 4 * j + 1][r] = vv.y;
            vsT[c + 4 * j + 2][r] = vv.z; vsT[c + 4 * j + 3][r] = vv.w;
        }
    }
    __syncthreads();

    const int tm = (tid >> 4) * 4;
    const int tn = (tid & 15) * 4;
    float acc[4][4];
#pragma unroll
    for (int i = 0; i < 4; i++)
#pragma unroll
        for (int j = 0; j < 4; j++) acc[i][j] = 0.f;

#pragma unroll
    for (int s = 0; s < 64; s++) {
        const float4 av = *(const float4*)&hsT[s][tm];
        const float4 bv = *(const float4*)&vsT[s][tn];
        const float a4[4] = {av.x, av.y, av.z, av.w};
        const float b4[4] = {bv.x, bv.y, bv.z, bv.w};
#pragma unroll
        for (int i = 0; i < 4; i++)
#pragma unroll
            for (int j = 0; j < 4; j++) acc[i][j] += a4[i] * b4[j];
    }

#pragma unroll
    for (int i = 0; i < 4; i++) {
        float v[4];
#pragma unroll
        for (int j = 0; j < 4; j++) {
            v[j] = acc[i][j] + bias[n0 + tn + j];
            if (RELU) v[j] = fmaxf(v[j], 0.f);
        }
        const size_t o = (size_t)(m0 + tm + i) * ND + (n0 + tn);
        if (BF16OUT) {
            __nv_bfloat16 hh[4], ll[4];
#pragma unroll
            for (int j = 0; j < 4; j++) {
                hh[j] = __float2bfloat16_rn(v[j]);
                ll[j] = __float2bfloat16_rn(v[j] - __bfloat162float(hh[j]));
            }
            *(__nv_bfloat162*)(ohi + o)     = __halves2bfloat162(hh[0], hh[1]);
            *(__nv_bfloat162*)(ohi + o + 2) = __halves2bfloat162(hh[2], hh[3]);
            *(__nv_bfloat162*)(olo + o)     = __halves2bfloat162(ll[0], ll[1]);
            *(__nv_bfloat162*)(olo + o + 2) = __halves2bfloat162(ll[2], ll[3]);
        } else {
            *(float4*)(out + o) = make_float4(v[0], v[1], v[2], v[3]);
        }
    }
}

// ---------------------------------------------------------------------------
// fp32 -> bf16 hi/lo split (elementwise, float4 vectorized)
// ---------------------------------------------------------------------------
__global__ __launch_bounds__(256)
void conv_split(const float4* __restrict__ in, __nv_bfloat162* __restrict__ hi,
                __nv_bfloat162* __restrict__ lo, int n4)
{
    const int i = blockIdx.x * 256 + threadIdx.x;
    if (i >= n4) return;
    const float4 v = in[i];
    float f[4] = {v.x, v.y, v.z, v.w};
    __nv_bfloat16 hh[4], ll[4];
#pragma unroll
    for (int j = 0; j < 4; j++) {
        hh[j] = __float2bfloat16_rn(f[j]);
        ll[j] = __float2bfloat16_rn(f[j] - __bfloat162float(hh[j]));
    }
    hi[2 * i]     = __halves2bfloat162(hh[0], hh[1]);
    hi[2 * i + 1] = __halves2bfloat162(hh[2], hh[3]);
    lo[2 * i]     = __halves2bfloat162(ll[0], ll[1]);
    lo[2 * i + 1] = __halves2bfloat162(ll[2], ll[3]);
}

// U [64 x 1024] -> padded [128 x 1024] hi/lo with zero rows 64..127
__global__ __launch_bounds__(256)
void conv_upad(const float* __restrict__ U, __nv_bfloat162* __restrict__ hi,
               __nv_bfloat162* __restrict__ lo)
{
    const int i = blockIdx.x * 256 + threadIdx.x;   // over 128*1024/4 groups
    if (i >= GBM * ND / 4) return;
    const int row = (i * 4) >> 10;
    float4 v = make_float4(0.f, 0.f, 0.f, 0.f);
    if (row < NR) v = ((const float4*)U)[i];
    float f[4] = {v.x, v.y, v.z, v.w};
    __nv_bfloat16 hh[4], ll[4];
#pragma unroll
    for (int j = 0; j < 4; j++) {
        hh[j] = __float2bfloat16_rn(f[j]);
        ll[j] = __float2bfloat16_rn(f[j] - __bfloat162float(hh[j]));
    }
    hi[2 * i]     = __halves2bfloat162(hh[0], hh[1]);
    hi[2 * i + 1] = __halves2bfloat162(hh[2], hh[3]);
    lo[2 * i]     = __halves2bfloat162(ll[0], ll[1]);
    lo[2 * i + 1] = __halves2bfloat162(ll[2], ll[3]);
}

// ---------------------------------------------------------------------------
extern "C" void kernel_launch(void* const* d_in, const int* in_sizes, int n_in,
                              void* d_out, int out_size)
{
    const float* x = (const float*)d_in[0];

    __nv_bfloat16 *xhi, *xlo, *whi, *wlo, *uhi, *ulo;
    float *u2, *hp, *h;
    cudaGetSymbolAddress((void**)&xhi, g_xhi);
    cudaGetSymbolAddress((void**)&xlo, g_xlo);
    cudaGetSymbolAddress((void**)&whi, g_whi);
    cudaGetSymbolAddress((void**)&wlo, g_wlo);
    cudaGetSymbolAddress((void**)&uhi, g_uhi);
    cudaGetSymbolAddress((void**)&ulo, g_ulo);
    cudaGetSymbolAddress((void**)&u2, g_u2);
    cudaGetSymbolAddress((void**)&hp, g_hp);
    cudaGetSymbolAddress((void**)&h,  g_h);

    cudaFuncSetAttribute(gemm3bf16<0>, cudaFuncAttributeMaxDynamicSharedMemorySize, DSMEM_REQ);
    cudaFuncSetAttribute(gemm3bf16<1>, cudaFuncAttributeMaxDynamicSharedMemorySize, DSMEM_REQ);

    // split layer-0 input
    conv_split<<<(NB * ND / 4 + 255) / 256, 256>>>(
        (const float4*)x, (__nv_bfloat162*)xhi, (__nv_bfloat162*)xlo, NB * ND / 4);

    for (int l = 0; l < 3; l++) {
        const float* Wm   = (const float*)d_in[1 + 5 * l + 0];
        const float* bm   = (const float*)d_in[1 + 5 * l + 1];
        const float* U    = (const float*)d_in[1 + 5 * l + 2];
        const float* V    = (const float*)d_in[1 + 5 * l + 3];
        const float* bias = (const float*)d_in[1 + 5 * l + 4];

        // split weights
        conv_split<<<(NRR * ND / 4 + 255) / 256, 256>>>(
            (const float4*)Wm, (__nv_bfloat162*)whi, (__nv_bfloat162*)wlo, NRR * ND / 4);
        conv_upad<<<(GBM * ND / 4 + 255) / 256, 256>>>(
            U, (__nv_bfloat162*)uhi, (__nv_bfloat162*)ulo);

        // u = X @ U^T, K-split into 2 partial slices (128 CTAs)
        gemm3bf16<0><<<dim3(2, NB / GBM), 256, DSMEM_REQ>>>(
            xhi, xlo, uhi, ulo, nullptr, nullptr, u2);

        // W-gen GEMM + fused contract -> 32-way partials of h
        gemm3bf16<1><<<dim3(NT_W, NB / GBM), 256, DSMEM_REQ>>>(
            xhi, xlo, whi, wlo, u2, bm, hp);

        reduce_h<<<NB * NR / 256, 256>>>(hp, h);

        // out = act(h @ V^T + b); layers 0,1 emit bf16 hi/lo for next GEMM
        if (l < 2)
            vgemm_k<true, true><<<dim3(ND / 64, NB / 64), 256>>>(
                h, V, bias, nullptr, xhi, xlo);
        else
            vgemm_k<false, false><<<dim3(ND / 64, NB / 64), 256>>>(
                h, V, bias, (float*)d_out, nullptr, nullptr);
    }
}

// round 12
// speedup vs baseline: 1.8776x; 1.0545x over previous
#include <cuda_runtime.h>
#include <cuda_bf16.h>
#include <cstdint>

// ---------------- problem constants ----------------
#define NB   8192
#define ND   1024
#define NR   64
#define NRR  4096

// ---------------- GEMM tiling ----------------
#define GBM 128              // CTA M tile
#define GBN 128              // CTA N tile
#define NT_W (NRR / GBN)     // 32 N-tiles for W gemm
#define BKE  32              // bf16 K elems per stage (16 u32 per row)
#define LDS_W 20             // u32 row stride (16 + 4 skew) = 80B
#define MAT_BYTES (GBM * LDS_W * 4)          // 10240 per matrix tile
#define STAGE_BYTES (4 * MAT_BYTES)          // Ahi,Alo,Bhi,Blo = 40960
#define DSMEM_REQ (2 * STAGE_BYTES)          // 81920 -> 2 CTAs/SM

// ---------------- static device scratch ----------------
__device__ __nv_bfloat16 g_xhi[(size_t)NB * ND];
__device__ __nv_bfloat16 g_xlo[(size_t)NB * ND];
__device__ __nv_bfloat16 g_whi[(size_t)NRR * ND];
__device__ __nv_bfloat16 g_wlo[(size_t)NRR * ND];
__device__ __nv_bfloat16 g_uhi[(size_t)GBM * ND];   // U padded to 128 rows
__device__ __nv_bfloat16 g_ulo[(size_t)GBM * ND];
__device__ float g_u2[(size_t)2 * NB * NR];         // 2 K-slice partials of u
__device__ float g_hp[(size_t)NB * NT_W * NR];      // 32-way partials of h
__device__ float g_h [(size_t)NB * NR];

// ---------------- helpers ----------------
__device__ __forceinline__ uint32_t smem_u32(const void* p) {
    uint32_t a;
    asm("{ .reg .u64 t; cvta.to.shared.u64 t, %1; cvt.u32.u64 %0, t; }"
        : "=r"(a) : "l"(p));
    return a;
}
__device__ __forceinline__ void cpa16(uint32_t s, const void* g) {
    asm volatile("cp.async.cg.shared.global [%0], [%1], 16;\n" :: "r"(s), "l"(g));
}
#define CP_COMMIT() asm volatile("cp.async.commit_group;\n" ::: "memory")
#define CP_WAIT(n)  asm volatile("cp.async.wait_group %0;\n" :: "n"(n) : "memory")

#define MMA_BF16(acc, a0, a1, a2, a3, b0, b1)                                  \
    asm("mma.sync.aligned.m16n8k16.row.col.f32.bf16.bf16.f32 "                 \
        "{%0,%1,%2,%3}, {%4,%5,%6,%7}, {%8,%9}, {%0,%1,%2,%3};\n"              \
        : "+f"(acc[0]), "+f"(acc[1]), "+f"(acc[2]), "+f"(acc[3])               \
        : "r"(a0), "r"(a1), "r"(a2), "r"(a3), "r"(b0), "r"(b1))

#define LDSM_X4(r, addr)                                                       \
    asm volatile("ldmatrix.sync.aligned.m8n8.x4.shared.b16 {%0,%1,%2,%3}, [%4];" \
        : "=r"((r)[0]), "=r"((r)[1]), "=r"((r)[2]), "=r"((r)[3]) : "r"(addr))

// ---------------------------------------------------------------------------
// 3xBF16 mma.sync GEMM:  D[128 x 128] = A[128 x K] @ B[128 x K]^T
// ldmatrix.x4 fragment loads; 3 ILP passes per k-step: hi*hi, hi*lo, lo*hi.
// 2-stage cp.async pipeline, BKE=32 per stage -> 80KB smem -> 2 CTAs/SM.
// MODE 0: u-gemm, K-split: blockIdx.x = K-slice (0/1), each does K/2=512;
//         stores D cols [0,64) to out + slice*NB*NR.
// MODE 1: W-gen + fused contract: blockIdx.x = N-tile nt; emits
//         hp[m][nt][s] = sum_j u[m, nt*2+j] * (D[m, j*64+s] + bm[...]),
//         where u[m,r] = uvec[m*NR+r] + uvec[NB*NR + m*NR+r].
// ---------------------------------------------------------------------------
template<int MODE>
__global__ __launch_bounds__(256, 2)
void gemm3bf16(const __nv_bfloat16* __restrict__ Ahi_g, const __nv_bfloat16* __restrict__ Alo_g,
               const __nv_bfloat16* __restrict__ Bhi_g, const __nv_bfloat16* __restrict__ Blo_g,
               const float* __restrict__ uvec, const float* __restrict__ bmvec,
               float* __restrict__ out)
{
    extern __shared__ char dynsmem[];
    __shared__ float sbm[GBN];

    const uint32_t sbase = smem_u32(dynsmem);

    const int tid  = threadIdx.x;
    const int warp = tid >> 5;
    const int lane = tid & 31;
    const int wm = (warp & 3) * 32;               // warp M offset
    const int wn = (warp >> 2) * 64;              // warp N offset
    const int g  = lane >> 2;                     // 0..7
    const int tg = lane & 3;                      // 0..3

    const int nt = blockIdx.x;
    const int mt = blockIdx.y;
    const size_t arow0 = (size_t)mt * GBM;
    const size_t brow0 = (MODE == 0) ? 0 : (size_t)nt * GBN;
    const int kbase = (MODE == 0) ? nt * (ND / 2) : 0;
    const int nst   = (MODE == 0) ? (ND / 2) / BKE : ND / BKE;

    if (MODE == 1 && tid < GBN) sbm[tid] = bmvec[nt * GBN + tid];

    float acc[2][8][4];
#pragma unroll
    for (int i = 0; i < 2; i++)
#pragma unroll
        for (int j = 0; j < 8; j++)
#pragma unroll
            for (int k = 0; k < 4; k++) acc[i][j][k] = 0.f;

    // ---- per-lane ldmatrix byte offsets (within a matrix area) ----
    const int l8 = lane & 7;
    uint32_t aOffB[2], bOffB[4];
#pragma unroll
    for (int mf = 0; mf < 2; mf++)
        aOffB[mf] = (uint32_t)(((wm + mf * 16 + l8 + ((lane >> 3) & 1) * 8) * LDS_W
                                + (lane >> 4) * 4) * 4);
#pragma unroll
    for (int p = 0; p < 4; p++)
        bOffB[p] = (uint32_t)(((wn + p * 16 + l8 + ((lane >> 4) & 1) * 8) * LDS_W
                               + ((lane >> 3) & 1) * 4) * 4);

    // ---- stage loader: 4 matrices x 128 rows x 4 x16B; 8 cp.async/thread ----
    auto load_stage = [&](int stage, int buf) {
        const uint32_t base = sbase + buf * STAGE_BYTES;
        const int k0 = kbase + stage * BKE;
#pragma unroll
        for (int it = 0; it < 2; it++) {
            const int t = tid + it * 256;         // 0..511
            const int row = t >> 2, c = t & 3;
            const uint32_t so = (uint32_t)(row * (LDS_W * 4) + c * 16);
            const size_t ga = (arow0 + row) * ND + k0 + c * 8;
            const size_t gb = (brow0 + row) * ND + k0 + c * 8;
            cpa16(base + so,                 Ahi_g + ga);
            cpa16(base + MAT_BYTES + so,     Alo_g + ga);
            cpa16(base + 2 * MAT_BYTES + so, Bhi_g + gb);
            cpa16(base + 3 * MAT_BYTES + so, Blo_g + gb);
        }
        CP_COMMIT();
    };

    load_stage(0, 0);

    for (int i = 0; i < nst; i++) {
        if (i + 1 < nst) {
            load_stage(i + 1, (i + 1) & 1);
            CP_WAIT(1);
        } else {
            CP_WAIT(0);
        }
        __syncthreads();                          // stage i resident

        const uint32_t stb = sbase + (i & 1) * STAGE_BYTES;

#pragma unroll
        for (int ks = 0; ks < 2; ks++) {
            const uint32_t kob = (uint32_t)(ks * 32);   // 8 u32 = 32 bytes
            uint32_t ah[2][4], al[2][4], bh[4][4], bl[4][4];
#pragma unroll
            for (int mf = 0; mf < 2; mf++) {
                LDSM_X4(ah[mf], stb + aOffB[mf] + kob);
                LDSM_X4(al[mf], stb + MAT_BYTES + aOffB[mf] + kob);
            }
#pragma unroll
            for (int p = 0; p < 4; p++) {
                LDSM_X4(bh[p], stb + 2 * MAT_BYTES + bOffB[p] + kob);
                LDSM_X4(bl[p], stb + 3 * MAT_BYTES + bOffB[p] + kob);
            }
            // pass 1: hi*hi  (16 independent MMAs)
#pragma unroll
            for (int p = 0; p < 4; p++)
#pragma unroll
                for (int mf = 0; mf < 2; mf++) {
                    MMA_BF16(acc[mf][2 * p],     ah[mf][0], ah[mf][1], ah[mf][2], ah[mf][3], bh[p][0], bh[p][1]);
                    MMA_BF16(acc[mf][2 * p + 1], ah[mf][0], ah[mf][1], ah[mf][2], ah[mf][3], bh[p][2], bh[p][3]);
                }
            // pass 2: hi*lo
#pragma unroll
            for (int p = 0; p < 4; p++)
#pragma unroll
                for (int mf = 0; mf < 2; mf++) {
                    MMA_BF16(acc[mf][2 * p],     ah[mf][0], ah[mf][1], ah[mf][2], ah[mf][3], bl[p][0], bl[p][1]);
                    MMA_BF16(acc[mf][2 * p + 1], ah[mf][0], ah[mf][1], ah[mf][2], ah[mf][3], bl[p][2], bl[p][3]);
                }
            // pass 3: lo*hi
#pragma unroll
            for (int p = 0; p < 4; p++)
#pragma unroll
                for (int mf = 0; mf < 2; mf++) {
                    MMA_BF16(acc[mf][2 * p],     al[mf][0], al[mf][1], al[mf][2], al[mf][3], bh[p][0], bh[p][1]);
                    MMA_BF16(acc[mf][2 * p + 1], al[mf][0], al[mf][1], al[mf][2], al[mf][3], bh[p][2], bh[p][3]);
                }
        }
        __syncthreads();                          // all reads of buf done
    }

    if (MODE == 0) {
        // store cols [0,64) of D to u partial slice nt
        float* o = out + (size_t)nt * NB * NR;
        if (wn == 0) {
#pragma unroll
            for (int mf = 0; mf < 2; mf++) {
#pragma unroll
                for (int nf = 0; nf < 8; nf++) {
                    const size_t row = arow0 + wm + mf * 16 + g;
                    const int col = nf * 8 + tg * 2;
                    *(float2*)(o + row * NR + col) =
                        make_float2(acc[mf][nf][0], acc[mf][nf][1]);
                    *(float2*)(o + (row + 8) * NR + col) =
                        make_float2(acc[mf][nf][2], acc[mf][nf][3]);
                }
            }
        }
        return;
    }

    // ---- MODE 1: fused contract. part[128][65] fp32 reuses operand smem ----
    float* part = (float*)dynsmem;
    for (int idx = tid; idx < 128 * 65; idx += 256) part[idx] = 0.f;
    __syncthreads();

    const int j = warp >> 2;                      // r-block within tile (0/1)
    const int ridx = nt * 2 + j;
    float um[4];
#pragma unroll
    for (int mf = 0; mf < 2; mf++) {
        const size_t r0 = (arow0 + wm + mf * 16 + g) * NR + ridx;
        const size_t r1 = (arow0 + wm + mf * 16 + 8 + g) * NR + ridx;
        um[mf * 2 + 0] = uvec[r0] + uvec[(size_t)NB * NR + r0];
        um[mf * 2 + 1] = uvec[r1] + uvec[(size_t)NB * NR + r1];
    }

    // two phases so the two r-blocks never race on part[] (deterministic)
#pragma unroll
    for (int ph = 0; ph < 2; ph++) {
        if (j == ph) {
#pragma unroll
            for (int mf = 0; mf < 2; mf++) {
                const int r0 = wm + mf * 16 + g;
#pragma unroll
                for (int nf = 0; nf < 8; nf++) {
                    const int s0 = nf * 8 + tg * 2;
                    const float b0 = sbm[j * 64 + s0];
                    const float b1 = sbm[j * 64 + s0 + 1];
                    part[r0 * 65 + s0]           += um[mf * 2] * (acc[mf][nf][0] + b0);
                    part[r0 * 65 + s0 + 1]       += um[mf * 2] * (acc[mf][nf][1] + b1);
                    part[(r0 + 8) * 65 + s0]     += um[mf * 2 + 1] * (acc[mf][nf][2] + b0);
                    part[(r0 + 8) * 65 + s0 + 1] += um[mf * 2 + 1] * (acc[mf][nf][3] + b1);
                }
            }
        }
        __syncthreads();
    }

    // store hp[m][nt][s]
    for (int idx = tid; idx < 128 * 64; idx += 256) {
        const int row = idx >> 6, s = idx & 63;
        out[((arow0 + row) * NT_W + nt) * NR + s] = part[row * 65 + s];
    }
}

// ---------------------------------------------------------------------------
// h[m,s] = sum_t hp[m,t,s]
// ---------------------------------------------------------------------------
__global__ __launch_bounds__(256)
void reduce_h(const float* __restrict__ hp, float* __restrict__ h)
{
    const int idx = blockIdx.x * 256 + threadIdx.x;   // over NB*NR
    const int m = idx >> 6, s = idx & 63;
    const float* p = hp + (size_t)m * (NT_W * NR) + s;
    float a = 0.f;
#pragma unroll
    for (int t = 0; t < NT_W; t++) a += p[t * NR];
    h[idx] = a;
}

// ---------------------------------------------------------------------------
// out[m,n] = act( sum_s h[m,s] * V[n,s] + bias[n] )
// Transposed smem ([s][m] / [s][n], stride 68) -> float4 inner-loop reads.
// BF16OUT: emit hi/lo bf16 split directly (feeds next layer's GEMM)
// ---------------------------------------------------------------------------
template<bool RELU, bool BF16OUT>
__global__ __launch_bounds__(256)
void vgemm_k(const float* __restrict__ h, const float* __restrict__ V,
             const float* __restrict__ bias, float* __restrict__ out,
             __nv_bfloat16* __restrict__ ohi, __nv_bfloat16* __restrict__ olo)
{
    __shared__ float hsT[64][68];   // [s][m]
    __shared__ float vsT[64][68];   // [s][n]
    const int m0 = blockIdx.y * 64;
    const int n0 = blockIdx.x * 64;
    const int tid = threadIdx.x;

    {
        const int r = tid >> 2;          // 0..63
        const int c = (tid & 3) * 16;    // 0,16,32,48
        const float4* hp = (const float4*)(h + (size_t)(m0 + r) * NR + c);
        const float4* vp = (const float4*)(V + (size_t)(n0 + r) * NR + c);
#pragma unroll
        for (int j = 0; j < 4; j++) {
            float4 hv = hp[j];
            hsT[c + 4 * j + 0][r] = hv.x; hsT[c + 4 * j + 1][r] = hv.y;
            hsT[c + 4 * j + 2][r] = hv.z; hsT[c + 4 * j + 3][r] = hv.w;
            float4 vv = vp[j];
            vsT[c + 4 * j + 0][r] = vv.x; vsT[c + 4 * j + 1][r] = vv.y;
            vsT[c + 4 * j + 2][r] = vv.z; vsT[c + 4 * j + 3][r] = vv.w;
        }
    }
    __syncthreads();

    const int tm = (tid >> 4) * 4;
    const int tn = (tid & 15) * 4;
    float acc[4][4];
#pragma unroll
    for (int i = 0; i < 4; i++)
#pragma unroll
        for (int j = 0; j < 4; j++) acc[i][j] = 0.f;

#pragma unroll
    for (int s = 0; s < 64; s++) {
        const float4 av = *(const float4*)&hsT[s][tm];
        const float4 bv = *(const float4*)&vsT[s][tn];
        const float a4[4] = {av.x, av.y, av.z, av.w};
        const float b4[4] = {bv.x, bv.y, bv.z, bv.w};
#pragma unroll
        for (int i = 0; i < 4; i++)
#pragma unroll
            for (int j = 0; j < 4; j++) acc[i][j] += a4[i] * b4[j];
    }

#pragma unroll
    for (int i = 0; i < 4; i++) {
        float v[4];
#pragma unroll
        for (int j = 0; j < 4; j++) {
            v[j] = acc[i][j] + bias[n0 + tn + j];
            if (RELU) v[j] = fmaxf(v[j], 0.f);
        }
        const size_t o = (size_t)(m0 + tm + i) * ND + (n0 + tn);
        if (BF16OUT) {
            __nv_bfloat16 hh[4], ll[4];
#pragma unroll
            for (int j = 0; j < 4; j++) {
                hh[j] = __float2bfloat16_rn(v[j]);
                ll[j] = __float2bfloat16_rn(v[j] - __bfloat162float(hh[j]));
            }
            *(__nv_bfloat162*)(ohi + o)     = __halves2bfloat162(hh[0], hh[1]);
            *(__nv_bfloat162*)(ohi + o + 2) = __halves2bfloat162(hh[2], hh[3]);
            *(__nv_bfloat162*)(olo + o)     = __halves2bfloat162(ll[0], ll[1]);
            *(__nv_bfloat162*)(olo + o + 2) = __halves2bfloat162(ll[2], ll[3]);
        } else {
            *(float4*)(out + o) = make_float4(v[0], v[1], v[2], v[3]);
        }
    }
}

// ---------------------------------------------------------------------------
// fp32 -> bf16 hi/lo split (elementwise, float4 vectorized)
// ---------------------------------------------------------------------------
__global__ __launch_bounds__(256)
void conv_split(const float4* __restrict__ in, __nv_bfloat162* __restrict__ hi,
                __nv_bfloat162* __restrict__ lo, int n4)
{
    const int i = blockIdx.x * 256 + threadIdx.x;
    if (i >= n4) return;
    const float4 v = in[i];
    float f[4] = {v.x, v.y, v.z, v.w};
    __nv_bfloat16 hh[4], ll[4];
#pragma unroll
    for (int j = 0; j < 4; j++) {
        hh[j] = __float2bfloat16_rn(f[j]);
        ll[j] = __float2bfloat16_rn(f[j] - __bfloat162float(hh[j]));
    }
    hi[2 * i]     = __halves2bfloat162(hh[0], hh[1]);
    hi[2 * i + 1] = __halves2bfloat162(hh[2], hh[3]);
    lo[2 * i]     = __halves2bfloat162(ll[0], ll[1]);
    lo[2 * i + 1] = __halves2bfloat162(ll[2], ll[3]);
}

// U [64 x 1024] -> padded [128 x 1024] hi/lo with zero rows 64..127
__global__ __launch_bounds__(256)
void conv_upad(const float* __restrict__ U, __nv_bfloat162* __restrict__ hi,
               __nv_bfloat162* __restrict__ lo)
{
    const int i = blockIdx.x * 256 + threadIdx.x;   // over 128*1024/4 groups
    if (i >= GBM * ND / 4) return;
    const int row = (i * 4) >> 10;
    float4 v = make_float4(0.f, 0.f, 0.f, 0.f);
    if (row < NR) v = ((const float4*)U)[i];
    float f[4] = {v.x, v.y, v.z, v.w};
    __nv_bfloat16 hh[4], ll[4];
#pragma unroll
    for (int j = 0; j < 4; j++) {
        hh[j] = __float2bfloat16_rn(f[j]);
        ll[j] = __float2bfloat16_rn(f[j] - __bfloat162float(hh[j]));
    }
    hi[2 * i]     = __halves2bfloat162(hh[0], hh[1]);
    hi[2 * i + 1] = __halves2bfloat162(hh[2], hh[3]);
    lo[2 * i]     = __halves2bfloat162(ll[0], ll[1]);
    lo[2 * i + 1] = __halves2bfloat162(ll[2], ll[3]);
}

// ---------------------------------------------------------------------------
extern "C" void kernel_launch(void* const* d_in, const int* in_sizes, int n_in,
                              void* d_out, int out_size)
{
    const float* x = (const float*)d_in[0];

    __nv_bfloat16 *xhi, *xlo, *whi, *wlo, *uhi, *ulo;
    float *u2, *hp, *h;
    cudaGetSymbolAddress((void**)&xhi, g_xhi);
    cudaGetSymbolAddress((void**)&xlo, g_xlo);
    cudaGetSymbolAddress((void**)&whi, g_whi);
    cudaGetSymbolAddress((void**)&wlo, g_wlo);
    cudaGetSymbolAddress((void**)&uhi, g_uhi);
    cudaGetSymbolAddress((void**)&ulo, g_ulo);
    cudaGetSymbolAddress((void**)&u2, g_u2);
    cudaGetSymbolAddress((void**)&hp, g_hp);
    cudaGetSymbolAddress((void**)&h,  g_h);

    cudaFuncSetAttribute(gemm3bf16<0>, cudaFuncAttributeMaxDynamicSharedMemorySize, DSMEM_REQ);
    cudaFuncSetAttribute(gemm3bf16<1>, cudaFuncAttributeMaxDynamicSharedMemorySize, DSMEM_REQ);

    // split layer-0 input
    conv_split<<<(NB * ND / 4 + 255) / 256, 256>>>(
        (const float4*)x, (__nv_bfloat162*)xhi, (__nv_bfloat162*)xlo, NB * ND / 4);

    for (int l = 0; l < 3; l++) {
        const float* Wm   = (const float*)d_in[1 + 5 * l + 0];
        const float* bm   = (const float*)d_in[1 + 5 * l + 1];
        const float* U    = (const float*)d_in[1 + 5 * l + 2];
        const float* V    = (const float*)d_in[1 + 5 * l + 3];
        const float* bias = (const float*)d_in[1 + 5 * l + 4];

        // split weights
        conv_split<<<(NRR * ND / 4 + 255) / 256, 256>>>(
            (const float4*)Wm, (__nv_bfloat162*)whi, (__nv_bfloat162*)wlo, NRR * ND / 4);
        conv_upad<<<(GBM * ND / 4 + 255) / 256, 256>>>(
            U, (__nv_bfloat162*)uhi, (__nv_bfloat162*)ulo);

        // u = X @ U^T, K-split into 2 partial slices (128 CTAs)
        gemm3bf16<0><<<dim3(2, NB / GBM), 256, DSMEM_REQ>>>(
            xhi, xlo, uhi, ulo, nullptr, nullptr, u2);

        // W-gen GEMM + fused contract -> 32-way partials of h
        gemm3bf16<1><<<dim3(NT_W, NB / GBM), 256, DSMEM_REQ>>>(
            xhi, xlo, whi, wlo, u2, bm, hp);

        reduce_h<<<NB * NR / 256, 256>>>(hp, h);

        // out = act(h @ V^T + b); layers 0,1 emit bf16 hi/lo for next GEMM
        if (l < 2)
            vgemm_k<true, true><<<dim3(ND / 64, NB / 64), 256>>>(
                h, V, bias, nullptr, xhi, xlo);
        else
            vgemm_k<false, false><<<dim3(ND / 64, NB / 64), 256>>>(
                h, V, bias, (float*)d_out, nullptr, nullptr);
    }
}